// round 15
// baseline (speedup 1.0000x reference)
#include <cuda_runtime.h>
#include <cuda_bf16.h>
#include <cstdint>

#define NTOK 8192
#define DIM  256
#define BM   32
#define BK   32
#define NT   (NTOK / BK)     // 256 key tiles

#define LQB  264             // bf16 elements per smem row for Q/K (256 + 8 pad)
#define LDV  36              // floats (32 + 4 pad)
#define LDP  36

// smem byte offsets (single CTA = 109568 B; 2 CTAs/SM)
#define SM_QH   0
#define SM_QL   (SM_QH + 32 * LQB * 2)        // 16896
#define SM_KH   (SM_QL + 32 * LQB * 2)        // 33792
#define SM_KL   (SM_KH + 32 * LQB * 2)        // 50688
#define SM_VT   (SM_KL + 32 * LQB * 2)        // 67584
#define SM_PS   (SM_VT + 256 * LDV * 4)       // 104448
#define SM_RED  (SM_PS + 32 * LDP * 4)        // 109056
#define SM_TOT  (SM_RED + 64 * 8)             // 109568

// Scratch: Q,K as bf16 hi/lo pairs; V tf32-rounded fp32, TRANSPOSED [dim][ntok].
// Q is pre-scaled by log2(e) so softmax can use exp2 throughout.
__device__ __nv_bfloat16 g_Qh[NTOK * DIM];
__device__ __nv_bfloat16 g_Ql[NTOK * DIM];
__device__ __nv_bfloat16 g_Kh[NTOK * DIM];
__device__ __nv_bfloat16 g_Kl[NTOK * DIM];
__device__ float         g_VT[DIM * NTOK];

__device__ __forceinline__ float tf32_rna(float x) {
    uint32_t r;
    asm("cvt.rna.tf32.f32 %0, %1;" : "=r"(r) : "f"(x));
    return __uint_as_float(r);
}

// ---------------------------------------------------------------------------
// Projection GEMM (SIMT fp32). Q,K stored as bf16 hi/lo pairs (Q scaled by
// log2e); V stored transposed + tf32-RNA-rounded.
// ---------------------------------------------------------------------------
__global__ __launch_bounds__(256) void proj_kernel(
    const float* __restrict__ X,
    const float* __restrict__ WQ,
    const float* __restrict__ WK,
    const float* __restrict__ WV)
{
    __shared__ float As[64][36];
    __shared__ float Bs[32][64];

    const int tid  = threadIdx.x;
    const int tx   = tid & 15;
    const int ty   = tid >> 4;
    const int row0 = blockIdx.x * 64;
    const int wsel = blockIdx.y >> 2;
    const int colB = (blockIdx.y & 3) * 64;

    const float* __restrict__ W = (wsel == 0) ? WQ : (wsel == 1) ? WK : WV;

    float acc[4][4] = {};

    for (int k0 = 0; k0 < DIM; k0 += 32) {
        #pragma unroll
        for (int it = 0; it < 2; ++it) {
            int s  = tid + it * 256;
            int r  = s >> 3;
            int k4 = (s & 7) * 4;
            float4 v = *reinterpret_cast<const float4*>(X + (row0 + r) * DIM + k0 + k4);
            *reinterpret_cast<float4*>(&As[r][k4]) = v;
        }
        #pragma unroll
        for (int it = 0; it < 2; ++it) {
            int s  = tid + it * 256;
            int kk = s >> 4;
            int c4 = (s & 15) * 4;
            float4 v = *reinterpret_cast<const float4*>(W + (k0 + kk) * DIM + colB + c4);
            *reinterpret_cast<float4*>(&Bs[kk][c4]) = v;
        }
        __syncthreads();

        #pragma unroll 8
        for (int kk = 0; kk < 32; ++kk) {
            float4 b = *reinterpret_cast<const float4*>(&Bs[kk][tx * 4]);
            float a0 = As[ty * 4 + 0][kk];
            float a1 = As[ty * 4 + 1][kk];
            float a2 = As[ty * 4 + 2][kk];
            float a3 = As[ty * 4 + 3][kk];
            acc[0][0] += a0 * b.x; acc[0][1] += a0 * b.y; acc[0][2] += a0 * b.z; acc[0][3] += a0 * b.w;
            acc[1][0] += a1 * b.x; acc[1][1] += a1 * b.y; acc[1][2] += a1 * b.z; acc[1][3] += a1 * b.w;
            acc[2][0] += a2 * b.x; acc[2][1] += a2 * b.y; acc[2][2] += a2 * b.z; acc[2][3] += a2 * b.w;
            acc[3][0] += a3 * b.x; acc[3][1] += a3 * b.y; acc[3][2] += a3 * b.z; acc[3][3] += a3 * b.w;
        }
        __syncthreads();
    }

    if (wsel == 2) {
        #pragma unroll
        for (int j = 0; j < 4; ++j) {
            float4 v = make_float4(tf32_rna(acc[0][j]), tf32_rna(acc[1][j]),
                                   tf32_rna(acc[2][j]), tf32_rna(acc[3][j]));
            *reinterpret_cast<float4*>(g_VT + (colB + tx * 4 + j) * NTOK + row0 + ty * 4) = v;
        }
    } else {
        // Q is pre-scaled by log2(e) so the flash kernel can use exp2.
        const float qs = (wsel == 0) ? 1.4426950408889634f : 1.0f;
        __nv_bfloat16* Oh = (wsel == 0) ? g_Qh : g_Kh;
        __nv_bfloat16* Ol = (wsel == 0) ? g_Ql : g_Kl;
        #pragma unroll
        for (int i = 0; i < 4; ++i) {
            ushort4 hv, lv;
            unsigned short* hp = &hv.x;
            unsigned short* lp = &lv.x;
            #pragma unroll
            for (int j = 0; j < 4; ++j) {
                float x = acc[i][j] * qs;
                __nv_bfloat16 h = __float2bfloat16_rn(x);
                float r = x - __bfloat162float(h);
                __nv_bfloat16 l = __float2bfloat16_rn(r);
                hp[j] = __bfloat16_as_ushort(h);
                lp[j] = __bfloat16_as_ushort(l);
            }
            const int idx = (row0 + ty * 4 + i) * DIM + colB + tx * 4;
            *reinterpret_cast<ushort4*>(Oh + idx) = hv;
            *reinterpret_cast<ushort4*>(Ol + idx) = lv;
        }
    }
}

// ---------------------------------------------------------------------------
// Flash attention: bf16-pair QK^T + tf32 PV. 128 threads (4 warps) per CTA,
// 2 CTAs/SM. Single-buffered K,V, phase-offset cp.async pipeline.
// Every wait_group is followed by a __syncthreads BEFORE the data is read
// (cp.async completion is per-thread; cross-thread visibility needs the
// barrier after all threads have waited).
// ---------------------------------------------------------------------------
__device__ __forceinline__ uint32_t smem_u32(const void* p) {
    return (uint32_t)__cvta_generic_to_shared(p);
}

#define LDSM_X4(R0, R1, R2, R3, ADDR)                                          \
    asm volatile("ldmatrix.sync.aligned.m8n8.x4.shared.b16 {%0,%1,%2,%3}, [%4];" \
                 : "=r"(R0), "=r"(R1), "=r"(R2), "=r"(R3) : "r"(ADDR))

__device__ __forceinline__ void mma_tf32(float c[4],
    uint32_t a0, uint32_t a1, uint32_t a2, uint32_t a3,
    uint32_t b0, uint32_t b1)
{
    asm volatile(
        "mma.sync.aligned.m16n8k8.row.col.f32.tf32.tf32.f32 "
        "{%0,%1,%2,%3},{%4,%5,%6,%7},{%8,%9},{%0,%1,%2,%3};"
        : "+f"(c[0]), "+f"(c[1]), "+f"(c[2]), "+f"(c[3])
        : "r"(a0), "r"(a1), "r"(a2), "r"(a3), "r"(b0), "r"(b1));
}

__device__ __forceinline__ void mma_bf16(float c[4],
    uint32_t a0, uint32_t a1, uint32_t a2, uint32_t a3,
    uint32_t b0, uint32_t b1)
{
    asm volatile(
        "mma.sync.aligned.m16n8k16.row.col.f32.bf16.bf16.f32 "
        "{%0,%1,%2,%3},{%4,%5,%6,%7},{%8,%9},{%0,%1,%2,%3};"
        : "+f"(c[0]), "+f"(c[1]), "+f"(c[2]), "+f"(c[3])
        : "r"(a0), "r"(a1), "r"(a2), "r"(a3), "r"(b0), "r"(b1));
}

__device__ __forceinline__ void cp16(uint32_t dst_smem, const void* src_gmem) {
    asm volatile("cp.async.cg.shared.global [%0], [%1], 16;" :: "r"(dst_smem), "l"(src_gmem));
}

extern __shared__ char fa_smem[];

__global__ __launch_bounds__(128, 2) void flash_kernel(float* __restrict__ out)
{
    const uint32_t sm = smem_u32(fa_smem);
    float*  Ps  = reinterpret_cast<float*>(fa_smem + SM_PS);
    float2* red = reinterpret_cast<float2*>(fa_smem + SM_RED);   // [2][32]

    const int tid  = threadIdx.x;
    const int lane = tid & 31;
    const int wid  = tid >> 5;       // 0..3
    const int wr   = wid >> 1;       // row group (16 q-rows): 0..1
    const int wc   = wid & 1;        // key half / dim half
    const int g    = lane >> 2;
    const int t    = lane & 3;
    const int q0   = blockIdx.x * BM;

    // --- load Q hi/lo tiles into padded smem rows (32 rows x 256 bf16) ---
    for (int s = tid; s < 32 * 32; s += 128) {       // 16B chunks
        int r = s >> 5, c = s & 31;
        uint4 v = *reinterpret_cast<const uint4*>(g_Qh + (q0 + r) * DIM + c * 8);
        *reinterpret_cast<uint4*>(fa_smem + SM_QH + r * (LQB * 2) + c * 16) = v;
        uint4 w = *reinterpret_cast<const uint4*>(g_Ql + (q0 + r) * DIM + c * 8);
        *reinterpret_cast<uint4*>(fa_smem + SM_QL + r * (LQB * 2) + c * 16) = w;
    }

    // --- prologue: issue K(0) [group], then V(0) [group] ---
    {
        #pragma unroll
        for (int i = 0; i < 8; ++i) {
            int s = tid + i * 128;                   // 1024 chunks of 16B
            int r = s >> 5, c = s & 31;
            cp16(sm + SM_KH + r * (LQB * 2) + c * 16, g_Kh + r * DIM + c * 8);
            cp16(sm + SM_KL + r * (LQB * 2) + c * 16, g_Kl + r * DIM + c * 8);
        }
        asm volatile("cp.async.commit_group;" ::: "memory");
        #pragma unroll
        for (int i = 0; i < 16; ++i) {
            int s = tid + i * 128;                   // 2048 chunks
            int d = s >> 3, c = s & 7;
            cp16(sm + SM_VT + d * (LDV * 4) + c * 16, g_VT + d * NTOK + c * 4);
        }
        asm volatile("cp.async.commit_group;" ::: "memory");
    }

    // ldmatrix lane byte-offsets
    const uint32_t q_off = (uint32_t)(wr * 16 + (lane & 15)) * (LQB * 2) + ((lane >> 4) << 4);
    const uint32_t k_off = (uint32_t)(wc * 16 + ((lane >> 4) << 3) + (lane & 7)) * (LQB * 2)
                           + (((lane >> 3) & 1) << 4);
    const uint32_t p_off = ((wr * 16 + (lane & 15)) * LDP + ((lane >> 4) << 2)) * 4u;
    const uint32_t v_off = ((wc * 128 + ((lane >> 4) << 3) + (lane & 7)) * LDV
                            + (((lane >> 3) & 1) << 2)) * 4u;

    const uint32_t qh_base = sm + SM_QH + q_off;
    const uint32_t ql_base = sm + SM_QL + q_off;
    const uint32_t kh_base = sm + SM_KH + k_off;
    const uint32_t kl_base = sm + SM_KL + k_off;
    const uint32_t ps_base = sm + SM_PS + p_off;
    const uint32_t vs_base = sm + SM_VT + v_off;

    float acc[16][4];
    #pragma unroll
    for (int i = 0; i < 16; ++i)
        #pragma unroll
        for (int j = 0; j < 4; ++j) acc[i][j] = 0.0f;

    float mrun0 = -1e30f, mrun1 = -1e30f;
    float lrun0 = 0.0f,   lrun1 = 0.0f;

    for (int tt = 0; tt < NT; ++tt) {
        // K(tt) complete for THIS thread (tt=0 also drains V0 — prologue only)
        asm volatile("cp.async.wait_group 0;" ::: "memory");
        // all threads waited -> K visible; PV(tt-1) done -> V buffer free;
        // Q stores visible at tt=0
        __syncthreads();

        if (tt > 0) {                                // issue V(tt) (overlaps S phase)
            const int k0 = tt * BK;
            #pragma unroll
            for (int i = 0; i < 16; ++i) {
                int s = tid + i * 128;
                int d = s >> 3, c = s & 7;
                cp16(sm + SM_VT + d * (LDV * 4) + c * 16, g_VT + d * NTOK + k0 + c * 4);
            }
            asm volatile("cp.async.commit_group;" ::: "memory");
        }

        // ---- S = Q K^T (bf16-pair, 3 terms): 16 rows x 16 keys per warp,
        // 16 k16-steps, 6 independent accumulator chains (term x ntile). ----
        float s3[3][2][4];
        #pragma unroll
        for (int a = 0; a < 3; ++a)
            #pragma unroll
            for (int b = 0; b < 2; ++b)
                #pragma unroll
                for (int c = 0; c < 4; ++c) s3[a][b][c] = 0.0f;

        #pragma unroll
        for (int kk = 0; kk < 16; ++kk) {
            uint32_t ah0, ah1, ah2, ah3, al0, al1, al2, al3;
            uint32_t bh0, bh1, bh2, bh3, bl0, bl1, bl2, bl3;
            LDSM_X4(ah0, ah1, ah2, ah3, qh_base + kk * 32u);
            LDSM_X4(al0, al1, al2, al3, ql_base + kk * 32u);
            LDSM_X4(bh0, bh1, bh2, bh3, kh_base + kk * 32u);
            LDSM_X4(bl0, bl1, bl2, bl3, kl_base + kk * 32u);
            mma_bf16(s3[0][0], ah0, ah1, ah2, ah3, bh0, bh1);   // hi*hi, n0
            mma_bf16(s3[0][1], ah0, ah1, ah2, ah3, bh2, bh3);   // hi*hi, n1
            mma_bf16(s3[1][0], ah0, ah1, ah2, ah3, bl0, bl1);   // hi*lo, n0
            mma_bf16(s3[1][1], ah0, ah1, ah2, ah3, bl2, bl3);   // hi*lo, n1
            mma_bf16(s3[2][0], al0, al1, al2, al3, bh0, bh1);   // lo*hi, n0
            mma_bf16(s3[2][1], al0, al1, al2, al3, bh2, bh3);   // lo*hi, n1
        }
        float sacc[2][4];
        #pragma unroll
        for (int b = 0; b < 2; ++b)
            #pragma unroll
            for (int c = 0; c < 4; ++c)
                sacc[b][c] = s3[0][b][c] + s3[1][b][c] + s3[2][b][c];

        // ---- softmax (online, exp2; scores pre-scaled by log2e) ----
        float m0h = fmaxf(fmaxf(sacc[0][0], sacc[0][1]), fmaxf(sacc[1][0], sacc[1][1]));
        float m1h = fmaxf(fmaxf(sacc[0][2], sacc[0][3]), fmaxf(sacc[1][2], sacc[1][3]));
        #pragma unroll
        for (int o = 1; o <= 2; o <<= 1) {
            m0h = fmaxf(m0h, __shfl_xor_sync(0xffffffffu, m0h, o));
            m1h = fmaxf(m1h, __shfl_xor_sync(0xffffffffu, m1h, o));
        }
        sacc[0][0] = exp2f(sacc[0][0] - m0h); sacc[0][1] = exp2f(sacc[0][1] - m0h);
        sacc[1][0] = exp2f(sacc[1][0] - m0h); sacc[1][1] = exp2f(sacc[1][1] - m0h);
        sacc[0][2] = exp2f(sacc[0][2] - m1h); sacc[0][3] = exp2f(sacc[0][3] - m1h);
        sacc[1][2] = exp2f(sacc[1][2] - m1h); sacc[1][3] = exp2f(sacc[1][3] - m1h);
        float l0h = sacc[0][0] + sacc[0][1] + sacc[1][0] + sacc[1][1];
        float l1h = sacc[0][2] + sacc[0][3] + sacc[1][2] + sacc[1][3];
        #pragma unroll
        for (int o = 1; o <= 2; o <<= 1) {
            l0h += __shfl_xor_sync(0xffffffffu, l0h, o);
            l1h += __shfl_xor_sync(0xffffffffu, l1h, o);
        }
        const int r0 = wr * 16 + g;
        if (t == 0) {
            red[wc * 32 + r0]     = make_float2(m0h, l0h);
            red[wc * 32 + r0 + 8] = make_float2(m1h, l1h);
        }
        __syncthreads();                             // sync2: S done (K free), red visible

        if (tt + 1 < NT) {                           // issue K(tt+1) (overlaps PV)
            const int k0 = (tt + 1) * BK;
            #pragma unroll
            for (int i = 0; i < 8; ++i) {
                int s = tid + i * 128;
                int r = s >> 5, c = s & 31;
                cp16(sm + SM_KH + r * (LQB * 2) + c * 16, g_Kh + (k0 + r) * DIM + c * 8);
                cp16(sm + SM_KL + r * (LQB * 2) + c * 16, g_Kl + (k0 + r) * DIM + c * 8);
            }
            asm volatile("cp.async.commit_group;" ::: "memory");
        }

        // merge halves -> tile (m_t, l_t), then online update (exp2)
        float2 fa0 = red[r0],        fb0 = red[32 + r0];
        float2 fa1 = red[r0 + 8],    fb1 = red[32 + r0 + 8];
        float mt0 = fmaxf(fa0.x, fb0.x);
        float lt0 = fa0.y * exp2f(fa0.x - mt0) + fb0.y * exp2f(fb0.x - mt0);
        float mt1 = fmaxf(fa1.x, fb1.x);
        float lt1 = fa1.y * exp2f(fa1.x - mt1) + fb1.y * exp2f(fb1.x - mt1);

        float mnew0 = fmaxf(mrun0, mt0);
        float sc0   = exp2f(mrun0 - mnew0);
        lrun0 = lrun0 * sc0 + lt0 * exp2f(mt0 - mnew0);
        float corr0 = exp2f(m0h - mnew0);
        mrun0 = mnew0;

        float mnew1 = fmaxf(mrun1, mt1);
        float sc1   = exp2f(mrun1 - mnew1);
        lrun1 = lrun1 * sc1 + lt1 * exp2f(mt1 - mnew1);
        float corr1 = exp2f(m1h - mnew1);
        mrun1 = mnew1;

        // rescale running O accumulators
        #pragma unroll
        for (int i = 0; i < 16; ++i) {
            acc[i][0] *= sc0; acc[i][1] *= sc0;
            acc[i][2] *= sc1; acc[i][3] *= sc1;
        }

        // store corrected P to smem, pre-rounded to tf32 RNA
        #pragma unroll
        for (int j = 0; j < 2; ++j) {
            int colb = wc * 16 + j * 8 + 2 * t;
            *reinterpret_cast<float2*>(Ps + r0 * LDP + colb) =
                make_float2(tf32_rna(sacc[j][0] * corr0), tf32_rna(sacc[j][1] * corr0));
            *reinterpret_cast<float2*>(Ps + (r0 + 8) * LDP + colb) =
                make_float2(tf32_rna(sacc[j][2] * corr1), tf32_rna(sacc[j][3] * corr1));
        }

        // V(tt) complete for THIS thread: pending = [V(tt), K(tt+1)] -> wait 1;
        // last tile has no K(tt+1) -> wait 0.
        if (tt + 1 < NT) {
            asm volatile("cp.async.wait_group 1;" ::: "memory");
        } else {
            asm volatile("cp.async.wait_group 0;" ::: "memory");
        }
        __syncthreads();                             // sync3: all waited -> V + Ps visible

        // ---- O += P V : tf32, 16 rows x 128 dims per warp ----
        #pragma unroll
        for (int ks = 0; ks < 4; ++ks) {
            uint32_t pa0, pa1, pa2, pa3;
            LDSM_X4(pa0, pa1, pa2, pa3, ps_base + ks * 32u);
            #pragma unroll
            for (int pr = 0; pr < 8; ++pr) {
                uint32_t b00, b01, b10, b11;
                LDSM_X4(b00, b01, b10, b11,
                        vs_base + (uint32_t)(pr * 16 * LDV * 4) + ks * 32u);
                mma_tf32(acc[pr * 2 + 0], pa0, pa1, pa2, pa3, b00, b01);
                mma_tf32(acc[pr * 2 + 1], pa0, pa1, pa2, pa3, b10, b11);
            }
        }
    }

    // ---- epilogue: normalize and store ----
    const float inv0 = 1.0f / lrun0;
    const float inv1 = 1.0f / lrun1;
    const int row0 = q0 + wr * 16 + g;
    #pragma unroll
    for (int i = 0; i < 16; ++i) {
        int col = wc * 128 + i * 8 + 2 * t;
        *reinterpret_cast<float2*>(out + row0 * DIM + col) =
            make_float2(acc[i][0] * inv0, acc[i][1] * inv0);
        *reinterpret_cast<float2*>(out + (row0 + 8) * DIM + col) =
            make_float2(acc[i][2] * inv1, acc[i][3] * inv1);
    }
}

// ---------------------------------------------------------------------------

extern "C" void kernel_launch(void* const* d_in, const int* in_sizes, int n_in,
                              void* d_out, int out_size)
{
    (void)in_sizes; (void)n_in; (void)out_size;
    const float* X  = (const float*)d_in[0];
    const float* WQ = (const float*)d_in[1];
    const float* WK = (const float*)d_in[2];
    const float* WV = (const float*)d_in[3];
    float* out = (float*)d_out;

    cudaFuncSetAttribute(flash_kernel, cudaFuncAttributeMaxDynamicSharedMemorySize, SM_TOT);

    proj_kernel<<<dim3(NTOK / 64, 12), 256>>>(X, WQ, WK, WV);
    flash_kernel<<<NTOK / BM, 128, SM_TOT>>>(out);
}

// round 16
// speedup vs baseline: 1.2152x; 1.2152x over previous
#include <cuda_runtime.h>
#include <cuda_bf16.h>
#include <cstdint>

#define NTOK 8192
#define DIM  256
#define BM   64
#define BK   64
#define NT   (NTOK / BK)     // 128 key tiles

#define LQB  264             // bf16 elements per smem row for Q/K (256 + 8 pad)
#define LDV  68              // floats (64 + 4 pad)
#define LDP  68

// smem byte offsets (single CTA, 1 CTA/SM, grid 128)
#define SM_QH   0
#define SM_QL   (SM_QH + 64 * LQB * 2)        // 33792
#define SM_KH   (SM_QL + 64 * LQB * 2)        // 67584
#define SM_KL   (SM_KH + 64 * LQB * 2)        // 101376
#define SM_VT   (SM_KL + 64 * LQB * 2)        // 135168
#define SM_PS   (SM_VT + 256 * LDV * 4)       // 204800
#define SM_RED  (SM_PS + 64 * LDP * 4)        // 222208
#define SM_TOT  (SM_RED + 128 * 8)            // 223232

// Scratch: Q,K as bf16 hi/lo pairs; V tf32-rounded fp32, TRANSPOSED [dim][ntok].
// Q is pre-scaled by log2(e) so softmax can use exp2 throughout.
__device__ __nv_bfloat16 g_Qh[NTOK * DIM];
__device__ __nv_bfloat16 g_Ql[NTOK * DIM];
__device__ __nv_bfloat16 g_Kh[NTOK * DIM];
__device__ __nv_bfloat16 g_Kl[NTOK * DIM];
__device__ float         g_VT[DIM * NTOK];

__device__ __forceinline__ float tf32_rna(float x) {
    uint32_t r;
    asm("cvt.rna.tf32.f32 %0, %1;" : "=r"(r) : "f"(x));
    return __uint_as_float(r);
}

// ---------------------------------------------------------------------------
// Projection GEMM (SIMT fp32). Q,K stored as bf16 hi/lo pairs (Q scaled by
// log2e); V stored transposed + tf32-RNA-rounded.
// ---------------------------------------------------------------------------
__global__ __launch_bounds__(256) void proj_kernel(
    const float* __restrict__ X,
    const float* __restrict__ WQ,
    const float* __restrict__ WK,
    const float* __restrict__ WV)
{
    __shared__ float As[64][36];
    __shared__ float Bs[32][64];

    const int tid  = threadIdx.x;
    const int tx   = tid & 15;
    const int ty   = tid >> 4;
    const int row0 = blockIdx.x * 64;
    const int wsel = blockIdx.y >> 2;
    const int colB = (blockIdx.y & 3) * 64;

    const float* __restrict__ W = (wsel == 0) ? WQ : (wsel == 1) ? WK : WV;

    float acc[4][4] = {};

    for (int k0 = 0; k0 < DIM; k0 += 32) {
        #pragma unroll
        for (int it = 0; it < 2; ++it) {
            int s  = tid + it * 256;
            int r  = s >> 3;
            int k4 = (s & 7) * 4;
            float4 v = *reinterpret_cast<const float4*>(X + (row0 + r) * DIM + k0 + k4);
            *reinterpret_cast<float4*>(&As[r][k4]) = v;
        }
        #pragma unroll
        for (int it = 0; it < 2; ++it) {
            int s  = tid + it * 256;
            int kk = s >> 4;
            int c4 = (s & 15) * 4;
            float4 v = *reinterpret_cast<const float4*>(W + (k0 + kk) * DIM + colB + c4);
            *reinterpret_cast<float4*>(&Bs[kk][c4]) = v;
        }
        __syncthreads();

        #pragma unroll 8
        for (int kk = 0; kk < 32; ++kk) {
            float4 b = *reinterpret_cast<const float4*>(&Bs[kk][tx * 4]);
            float a0 = As[ty * 4 + 0][kk];
            float a1 = As[ty * 4 + 1][kk];
            float a2 = As[ty * 4 + 2][kk];
            float a3 = As[ty * 4 + 3][kk];
            acc[0][0] += a0 * b.x; acc[0][1] += a0 * b.y; acc[0][2] += a0 * b.z; acc[0][3] += a0 * b.w;
            acc[1][0] += a1 * b.x; acc[1][1] += a1 * b.y; acc[1][2] += a1 * b.z; acc[1][3] += a1 * b.w;
            acc[2][0] += a2 * b.x; acc[2][1] += a2 * b.y; acc[2][2] += a2 * b.z; acc[2][3] += a2 * b.w;
            acc[3][0] += a3 * b.x; acc[3][1] += a3 * b.y; acc[3][2] += a3 * b.z; acc[3][3] += a3 * b.w;
        }
        __syncthreads();
    }

    if (wsel == 2) {
        #pragma unroll
        for (int j = 0; j < 4; ++j) {
            float4 v = make_float4(tf32_rna(acc[0][j]), tf32_rna(acc[1][j]),
                                   tf32_rna(acc[2][j]), tf32_rna(acc[3][j]));
            *reinterpret_cast<float4*>(g_VT + (colB + tx * 4 + j) * NTOK + row0 + ty * 4) = v;
        }
    } else {
        // Q is pre-scaled by log2(e) so the flash kernel can use exp2.
        const float qs = (wsel == 0) ? 1.4426950408889634f : 1.0f;
        __nv_bfloat16* Oh = (wsel == 0) ? g_Qh : g_Kh;
        __nv_bfloat16* Ol = (wsel == 0) ? g_Ql : g_Kl;
        #pragma unroll
        for (int i = 0; i < 4; ++i) {
            ushort4 hv, lv;
            unsigned short* hp = &hv.x;
            unsigned short* lp = &lv.x;
            #pragma unroll
            for (int j = 0; j < 4; ++j) {
                float x = acc[i][j] * qs;
                __nv_bfloat16 h = __float2bfloat16_rn(x);
                float r = x - __bfloat162float(h);
                __nv_bfloat16 l = __float2bfloat16_rn(r);
                hp[j] = __bfloat16_as_ushort(h);
                lp[j] = __bfloat16_as_ushort(l);
            }
            const int idx = (row0 + ty * 4 + i) * DIM + colB + tx * 4;
            *reinterpret_cast<ushort4*>(Oh + idx) = hv;
            *reinterpret_cast<ushort4*>(Ol + idx) = lv;
        }
    }
}

// ---------------------------------------------------------------------------
// Flash attention: bf16-pair QK^T + tf32 PV. 256 threads (8 warps), BK=64,
// grid 128 (1 CTA/SM). Single-buffered K,V, phase-offset cp.async pipeline
// (verified structure): V(tt) issued at tile top (overlaps S), K(tt+1)
// issued after post-S barrier (overlaps PV). Every wait_group is followed
// by a __syncthreads BEFORE the data is read.
// ---------------------------------------------------------------------------
__device__ __forceinline__ uint32_t smem_u32(const void* p) {
    return (uint32_t)__cvta_generic_to_shared(p);
}

#define LDSM_X4(R0, R1, R2, R3, ADDR)                                          \
    asm volatile("ldmatrix.sync.aligned.m8n8.x4.shared.b16 {%0,%1,%2,%3}, [%4];" \
                 : "=r"(R0), "=r"(R1), "=r"(R2), "=r"(R3) : "r"(ADDR))

__device__ __forceinline__ void mma_tf32(float c[4],
    uint32_t a0, uint32_t a1, uint32_t a2, uint32_t a3,
    uint32_t b0, uint32_t b1)
{
    asm volatile(
        "mma.sync.aligned.m16n8k8.row.col.f32.tf32.tf32.f32 "
        "{%0,%1,%2,%3},{%4,%5,%6,%7},{%8,%9},{%0,%1,%2,%3};"
        : "+f"(c[0]), "+f"(c[1]), "+f"(c[2]), "+f"(c[3])
        : "r"(a0), "r"(a1), "r"(a2), "r"(a3), "r"(b0), "r"(b1));
}

__device__ __forceinline__ void mma_bf16(float c[4],
    uint32_t a0, uint32_t a1, uint32_t a2, uint32_t a3,
    uint32_t b0, uint32_t b1)
{
    asm volatile(
        "mma.sync.aligned.m16n8k16.row.col.f32.bf16.bf16.f32 "
        "{%0,%1,%2,%3},{%4,%5,%6,%7},{%8,%9},{%0,%1,%2,%3};"
        : "+f"(c[0]), "+f"(c[1]), "+f"(c[2]), "+f"(c[3])
        : "r"(a0), "r"(a1), "r"(a2), "r"(a3), "r"(b0), "r"(b1));
}

__device__ __forceinline__ void cp16(uint32_t dst_smem, const void* src_gmem) {
    asm volatile("cp.async.cg.shared.global [%0], [%1], 16;" :: "r"(dst_smem), "l"(src_gmem));
}

extern __shared__ char fa_smem[];

__global__ __launch_bounds__(256, 1) void flash_kernel(float* __restrict__ out)
{
    const uint32_t sm = smem_u32(fa_smem);
    float*  Ps  = reinterpret_cast<float*>(fa_smem + SM_PS);
    float2* red = reinterpret_cast<float2*>(fa_smem + SM_RED);   // [2][64]

    const int tid  = threadIdx.x;
    const int lane = tid & 31;
    const int wid  = tid >> 5;       // 0..7
    const int wr   = wid >> 1;       // row group (16 q-rows): 0..3
    const int wc   = wid & 1;        // key half (32 keys) / dim half (128 dims)
    const int g    = lane >> 2;
    const int t    = lane & 3;
    const int q0   = blockIdx.x * BM;

    // --- load Q hi/lo tiles into padded smem rows (64 rows x 256 bf16) ---
    for (int s = tid; s < 64 * 32; s += 256) {       // 16B chunks
        int r = s >> 5, c = s & 31;
        uint4 v = *reinterpret_cast<const uint4*>(g_Qh + (q0 + r) * DIM + c * 8);
        *reinterpret_cast<uint4*>(fa_smem + SM_QH + r * (LQB * 2) + c * 16) = v;
        uint4 w = *reinterpret_cast<const uint4*>(g_Ql + (q0 + r) * DIM + c * 8);
        *reinterpret_cast<uint4*>(fa_smem + SM_QL + r * (LQB * 2) + c * 16) = w;
    }

    // --- prologue: issue K(0) [group], then V(0) [group] ---
    {
        #pragma unroll
        for (int i = 0; i < 8; ++i) {
            int s = tid + i * 256;                   // 2048 chunks per array
            int r = s >> 5, c = s & 31;
            cp16(sm + SM_KH + r * (LQB * 2) + c * 16, g_Kh + r * DIM + c * 8);
            cp16(sm + SM_KL + r * (LQB * 2) + c * 16, g_Kl + r * DIM + c * 8);
        }
        asm volatile("cp.async.commit_group;" ::: "memory");
        #pragma unroll
        for (int i = 0; i < 16; ++i) {
            int s = tid + i * 256;                   // 4096 chunks
            int d = s >> 4, c = s & 15;
            cp16(sm + SM_VT + d * (LDV * 4) + c * 16, g_VT + d * NTOK + c * 4);
        }
        asm volatile("cp.async.commit_group;" ::: "memory");
    }

    // ldmatrix lane byte-offsets
    const uint32_t q_off = (uint32_t)(wr * 16 + (lane & 15)) * (LQB * 2) + ((lane >> 4) << 4);
    const uint32_t k_off = (uint32_t)(wc * 32 + ((lane >> 4) << 3) + (lane & 7)) * (LQB * 2)
                           + (((lane >> 3) & 1) << 4);
    const uint32_t p_off = ((wr * 16 + (lane & 15)) * LDP + ((lane >> 4) << 2)) * 4u;
    const uint32_t v_off = ((wc * 128 + ((lane >> 4) << 3) + (lane & 7)) * LDV
                            + (((lane >> 3) & 1) << 2)) * 4u;

    const uint32_t qh_base = sm + SM_QH + q_off;
    const uint32_t ql_base = sm + SM_QL + q_off;
    const uint32_t kh_base = sm + SM_KH + k_off;
    const uint32_t kl_base = sm + SM_KL + k_off;
    const uint32_t ps_base = sm + SM_PS + p_off;
    const uint32_t vs_base = sm + SM_VT + v_off;

    float acc[16][4];
    #pragma unroll
    for (int i = 0; i < 16; ++i)
        #pragma unroll
        for (int j = 0; j < 4; ++j) acc[i][j] = 0.0f;

    float mrun0 = -1e30f, mrun1 = -1e30f;
    float lrun0 = 0.0f,   lrun1 = 0.0f;

    for (int tt = 0; tt < NT; ++tt) {
        // K(tt) complete for THIS thread (tt=0 also drains V0 — prologue only)
        asm volatile("cp.async.wait_group 0;" ::: "memory");
        // all threads waited -> K visible; PV(tt-1) done -> V buffer free;
        // Q stores visible at tt=0
        __syncthreads();

        if (tt > 0) {                                // issue V(tt) (overlaps S phase)
            const int k0 = tt * BK;
            #pragma unroll
            for (int i = 0; i < 16; ++i) {
                int s = tid + i * 256;
                int d = s >> 4, c = s & 15;
                cp16(sm + SM_VT + d * (LDV * 4) + c * 16, g_VT + d * NTOK + k0 + c * 4);
            }
            asm volatile("cp.async.commit_group;" ::: "memory");
        }

        // ---- S = Q K^T (bf16-pair, 3 terms): 16 rows x 32 keys per warp,
        // 16 k16-steps, 8 independent accumulator chains:
        //   sA[j] (hi*hi) and sB[j] (hi*lo + lo*hi), j = 4 n-tiles of 8 keys.
        float sA[4][4], sB[4][4];
        #pragma unroll
        for (int j = 0; j < 4; ++j)
            #pragma unroll
            for (int c = 0; c < 4; ++c) { sA[j][c] = 0.0f; sB[j][c] = 0.0f; }

        #pragma unroll
        for (int kk = 0; kk < 16; ++kk) {
            uint32_t ah0, ah1, ah2, ah3, al0, al1, al2, al3;
            uint32_t bh[8], bl[8];
            LDSM_X4(ah0, ah1, ah2, ah3, qh_base + kk * 32u);
            LDSM_X4(al0, al1, al2, al3, ql_base + kk * 32u);
            LDSM_X4(bh[0], bh[1], bh[2], bh[3], kh_base + kk * 32u);
            LDSM_X4(bh[4], bh[5], bh[6], bh[7], kh_base + 16u * (LQB * 2) + kk * 32u);
            LDSM_X4(bl[0], bl[1], bl[2], bl[3], kl_base + kk * 32u);
            LDSM_X4(bl[4], bl[5], bl[6], bl[7], kl_base + 16u * (LQB * 2) + kk * 32u);
            #pragma unroll
            for (int j = 0; j < 4; ++j) {
                mma_bf16(sA[j], ah0, ah1, ah2, ah3, bh[j * 2], bh[j * 2 + 1]);   // hi*hi
                mma_bf16(sB[j], ah0, ah1, ah2, ah3, bl[j * 2], bl[j * 2 + 1]);   // hi*lo
                mma_bf16(sB[j], al0, al1, al2, al3, bh[j * 2], bh[j * 2 + 1]);   // lo*hi
            }
        }
        float sacc[4][4];
        #pragma unroll
        for (int j = 0; j < 4; ++j)
            #pragma unroll
            for (int c = 0; c < 4; ++c) sacc[j][c] = sA[j][c] + sB[j][c];

        // ---- softmax (online, exp2; scores pre-scaled by log2e) ----
        float m0h = fmaxf(fmaxf(sacc[0][0], sacc[0][1]), fmaxf(sacc[1][0], sacc[1][1]));
        m0h = fmaxf(m0h, fmaxf(fmaxf(sacc[2][0], sacc[2][1]), fmaxf(sacc[3][0], sacc[3][1])));
        float m1h = fmaxf(fmaxf(sacc[0][2], sacc[0][3]), fmaxf(sacc[1][2], sacc[1][3]));
        m1h = fmaxf(m1h, fmaxf(fmaxf(sacc[2][2], sacc[2][3]), fmaxf(sacc[3][2], sacc[3][3])));
        #pragma unroll
        for (int o = 1; o <= 2; o <<= 1) {
            m0h = fmaxf(m0h, __shfl_xor_sync(0xffffffffu, m0h, o));
            m1h = fmaxf(m1h, __shfl_xor_sync(0xffffffffu, m1h, o));
        }
        float l0h = 0.0f, l1h = 0.0f;
        #pragma unroll
        for (int j = 0; j < 4; ++j) {
            sacc[j][0] = exp2f(sacc[j][0] - m0h); sacc[j][1] = exp2f(sacc[j][1] - m0h);
            sacc[j][2] = exp2f(sacc[j][2] - m1h); sacc[j][3] = exp2f(sacc[j][3] - m1h);
            l0h += sacc[j][0] + sacc[j][1];
            l1h += sacc[j][2] + sacc[j][3];
        }
        #pragma unroll
        for (int o = 1; o <= 2; o <<= 1) {
            l0h += __shfl_xor_sync(0xffffffffu, l0h, o);
            l1h += __shfl_xor_sync(0xffffffffu, l1h, o);
        }
        const int r0 = wr * 16 + g;
        if (t == 0) {
            red[wc * 64 + r0]     = make_float2(m0h, l0h);
            red[wc * 64 + r0 + 8] = make_float2(m1h, l1h);
        }
        __syncthreads();                             // sync2: S done (K free), red visible

        if (tt + 1 < NT) {                           // issue K(tt+1) (overlaps PV)
            const int k0 = (tt + 1) * BK;
            #pragma unroll
            for (int i = 0; i < 8; ++i) {
                int s = tid + i * 256;
                int r = s >> 5, c = s & 31;
                cp16(sm + SM_KH + r * (LQB * 2) + c * 16, g_Kh + (k0 + r) * DIM + c * 8);
                cp16(sm + SM_KL + r * (LQB * 2) + c * 16, g_Kl + (k0 + r) * DIM + c * 8);
            }
            asm volatile("cp.async.commit_group;" ::: "memory");
        }

        // merge the 2 key-half partials -> tile (m_t, l_t), online update (exp2)
        float2 fa0 = red[r0],        fb0 = red[64 + r0];
        float2 fa1 = red[r0 + 8],    fb1 = red[64 + r0 + 8];
        float mt0 = fmaxf(fa0.x, fb0.x);
        float lt0 = fa0.y * exp2f(fa0.x - mt0) + fb0.y * exp2f(fb0.x - mt0);
        float mt1 = fmaxf(fa1.x, fb1.x);
        float lt1 = fa1.y * exp2f(fa1.x - mt1) + fb1.y * exp2f(fb1.x - mt1);

        float mnew0 = fmaxf(mrun0, mt0);
        float sc0   = exp2f(mrun0 - mnew0);
        lrun0 = lrun0 * sc0 + lt0 * exp2f(mt0 - mnew0);
        float corr0 = exp2f(m0h - mnew0);
        mrun0 = mnew0;

        float mnew1 = fmaxf(mrun1, mt1);
        float sc1   = exp2f(mrun1 - mnew1);
        lrun1 = lrun1 * sc1 + lt1 * exp2f(mt1 - mnew1);
        float corr1 = exp2f(m1h - mnew1);
        mrun1 = mnew1;

        // rescale running O accumulators
        #pragma unroll
        for (int i = 0; i < 16; ++i) {
            acc[i][0] *= sc0; acc[i][1] *= sc0;
            acc[i][2] *= sc1; acc[i][3] *= sc1;
        }

        // store corrected P to smem, pre-rounded to tf32 RNA
        #pragma unroll
        for (int j = 0; j < 4; ++j) {
            int colb = wc * 32 + j * 8 + 2 * t;
            *reinterpret_cast<float2*>(Ps + r0 * LDP + colb) =
                make_float2(tf32_rna(sacc[j][0] * corr0), tf32_rna(sacc[j][1] * corr0));
            *reinterpret_cast<float2*>(Ps + (r0 + 8) * LDP + colb) =
                make_float2(tf32_rna(sacc[j][2] * corr1), tf32_rna(sacc[j][3] * corr1));
        }

        // V(tt) complete for THIS thread: pending = [V(tt), K(tt+1)] -> wait 1;
        // last tile has no K(tt+1) -> wait 0. (tt=0: V0 already drained at top.)
        if (tt + 1 < NT) {
            asm volatile("cp.async.wait_group 1;" ::: "memory");
        } else {
            asm volatile("cp.async.wait_group 0;" ::: "memory");
        }
        __syncthreads();                             // sync3: all waited -> V + Ps visible

        // ---- O += P V : tf32, 16 rows x 128 dims per warp, 8 k8-steps ----
        #pragma unroll
        for (int ks = 0; ks < 8; ++ks) {
            uint32_t pa0, pa1, pa2, pa3;
            LDSM_X4(pa0, pa1, pa2, pa3, ps_base + ks * 32u);
            #pragma unroll
            for (int pr = 0; pr < 8; ++pr) {
                uint32_t b00, b01, b10, b11;
                LDSM_X4(b00, b01, b10, b11,
                        vs_base + (uint32_t)(pr * 16 * LDV * 4) + ks * 32u);
                mma_tf32(acc[pr * 2 + 0], pa0, pa1, pa2, pa3, b00, b01);
                mma_tf32(acc[pr * 2 + 1], pa0, pa1, pa2, pa3, b10, b11);
            }
        }
    }

    // ---- epilogue: normalize and store ----
    const float inv0 = 1.0f / lrun0;
    const float inv1 = 1.0f / lrun1;
    const int row0 = q0 + wr * 16 + g;
    #pragma unroll
    for (int i = 0; i < 16; ++i) {
        int col = wc * 128 + i * 8 + 2 * t;
        *reinterpret_cast<float2*>(out + row0 * DIM + col) =
            make_float2(acc[i][0] * inv0, acc[i][1] * inv0);
        *reinterpret_cast<float2*>(out + (row0 + 8) * DIM + col) =
            make_float2(acc[i][2] * inv1, acc[i][3] * inv1);
    }
}

// ---------------------------------------------------------------------------

extern "C" void kernel_launch(void* const* d_in, const int* in_sizes, int n_in,
                              void* d_out, int out_size)
{
    (void)in_sizes; (void)n_in; (void)out_size;
    const float* X  = (const float*)d_in[0];
    const float* WQ = (const float*)d_in[1];
    const float* WK = (const float*)d_in[2];
    const float* WV = (const float*)d_in[3];
    float* out = (float*)d_out;

    cudaFuncSetAttribute(flash_kernel, cudaFuncAttributeMaxDynamicSharedMemorySize, SM_TOT);

    proj_kernel<<<dim3(NTOK / 64, 12), 256>>>(X, WQ, WK, WV);
    flash_kernel<<<NTOK / BM, 256, SM_TOT>>>(out);
}